// round 9
// baseline (speedup 1.0000x reference)
#include <cuda_runtime.h>

#define THREADS 128
#define Jt 32
#define NT 32          // 1024 / Jt
#define DEPTH 3
#define TILEB (Jt * 17 * 16)

typedef unsigned long long u64;
typedef unsigned int u32;

__device__ __forceinline__ float tanh_apx(float x) {
    float r; asm("tanh.approx.f32 %0, %1;" : "=f"(r) : "f"(x)); return r;
}
__device__ __forceinline__ float rcp_apx(float x) {
    float r; asm("rcp.approx.f32 %0, %1;" : "=f"(r) : "f"(x)); return r;
}
#define FMA2(d,a,b,c)  asm("fma.rn.f32x2 %0, %1, %2, %3;" : "=l"(d) : "l"(a), "l"(b), "l"(c))
#define ADD2(d,a,b)    asm("add.rn.f32x2 %0, %1, %2;" : "=l"(d) : "l"(a), "l"(b))
#define PACK2(d,x,y)   asm("mov.b64 %0, {%1,%2};" : "=l"(d) : "f"(x), "f"(y))
#define UNPACK2(x,y,d) asm("mov.b64 {%0,%1}, %2;" : "=f"(x), "=f"(y) : "l"(d))
#define CP16(dst,src)  asm volatile("cp.async.cg.shared.global [%0], [%1], 16;" :: "r"(dst), "l"(src))
#define CPCOMMIT()     asm volatile("cp.async.commit_group;")
#define CPWAIT1()      asm volatile("cp.async.wait_group 1;")

#define LOG2E 1.4426950408889634f
#define LN2   0.6931471805599453f
#define MAGICF 12582912.0f            // 1.5 * 2^23

__global__ __launch_bounds__(THREADS, 4)
void attn_mlp_kernel(const float* __restrict__ Q, const float* __restrict__ K,
                     const float* __restrict__ bias, const float* __restrict__ mask,
                     float* __restrict__ out, float* __restrict__ attn)
{
    __shared__ float4 ksm[DEPTH][Jt * 17];   // K tile ring, pad 17 -> conflict-free
    __shared__ float  red[4 * 64];
    __shared__ float  cbuf[4];

    const int tid = threadIdx.x;
    const int w   = tid >> 5, l = tid & 31;
    const int jl  = w * 8 + (l & 7);     // j within tile (0..31)
    const int cg  = l >> 3;              // channel group (16 ch each)

    const int row = blockIdx.x;          // one i-row per block
    const int b   = row >> 10;

    // pair 0 -> tanh (prescale 0.5); pairs 1..7 -> poly (prescale -log2e, so
    // s = -log2e*(qk+b) and sigma = 1/(1+2^s)).
    u64 q2[8], b2[8], acc[8];
    float Bp = 0.f;                      // sum of raw bias over this thread's poly channels
    {
        const float* qp = Q + (size_t)row * 64 + cg * 16;
        const float* bp = bias + cg * 16;
#pragma unroll
        for (int p = 0; p < 8; ++p) {
            float sc = (p == 0) ? 0.5f : -LOG2E;
            PACK2(q2[p], sc * qp[2*p], sc * qp[2*p+1]);
            PACK2(b2[p], sc * bp[2*p], sc * bp[2*p+1]);
            acc[p] = 0ull;
            if (p > 0) Bp += bp[2*p] + bp[2*p+1];
        }
    }
    float cnt = 0.f;

    u64 MG2, NEG1, C3p, C2p, C1p, ONE2;
    PACK2(MG2,  MAGICF, MAGICF);
    PACK2(NEG1, -1.0f, -1.0f);
    PACK2(C3p, 0.05582818f, 0.05582818f);
    PACK2(C2p, 0.24013972f, 0.24013972f);
    PACK2(C1p, 0.69314718f, 0.69314718f);
    PACK2(ONE2, 1.0f, 1.0f);

    const float4* Kg   = (const float4*)K + (size_t)b * 1024 * 16;
    const float*  mrow = mask + (size_t)row * 1024;
    float*        arow = attn + (size_t)row * 1024;

    // cp.async staging: 4 float4 per thread per tile
    const u32 smbase = (u32)__cvta_generic_to_shared(ksm);
    u32 doff[4]; int eoff[4];
#pragma unroll
    for (int u = 0; u < 4; ++u) {
        int f = u * 128 + tid;
        doff[u] = (u32)(((f >> 4) * 17 + (f & 15)) << 4);
        eoff[u] = (f >> 4) * 16 + (f & 15);
    }
    // prologue: tiles 0 and 1
#pragma unroll
    for (int t = 0; t < 2; ++t) {
#pragma unroll
        for (int u = 0; u < 4; ++u)
            CP16(smbase + t * TILEB + doff[u], (const void*)(Kg + t * 512 + eoff[u]));
        CPCOMMIT();
    }

    int buf = 0;
    for (int tile = 0; tile < NT; ++tile) {
        CPWAIT1();            // this tile's group done (<=1 newer pending)
        __syncthreads();

        // prefetch tile+2 into ring slot (commit always: keeps group count in sync)
        if (tile + 2 < NT) {
            int nb = buf + 2; if (nb >= DEPTH) nb -= DEPTH;
#pragma unroll
            for (int u = 0; u < 4; ++u)
                CP16(smbase + nb * TILEB + doff[u],
                     (const void*)(Kg + (tile + 2) * 512 + eoff[u]));
        }
        CPCOMMIT();

        const int   j = tile * Jt + jl;
        const float m = mrow[j];
        u64 m2; PACK2(m2, m, m);

        u64 k2[8];
        {
            const float4* kb4 = &ksm[buf][jl * 17 + cg * 4];
#pragma unroll
            for (int p4 = 0; p4 < 4; ++p4) {
                float4 kv = kb4[p4];
                PACK2(k2[2*p4],   kv.x, kv.y);
                PACK2(k2[2*p4+1], kv.z, kv.w);
            }
        }

        u64 dA = 0ull;   // tanh-pair dot partial (scale 0.5)
        u64 sa = 0ull;   // sum of poly s values (for attn reconstruction)

        // ---- pair 0: tanh path (MUFU) ----
        {
            u64 l2, t2; float la, lb;
            FMA2(l2, q2[0], k2[0], b2[0]);
            FMA2(dA, q2[0], k2[0], dA);
            UNPACK2(la, lb, l2);
            PACK2(t2, tanh_apx(la), tanh_apx(lb));
            FMA2(acc[0], m2, t2, acc[0]);
        }
        // ---- pairs 1..7: FMA-pipe exp2 poly; sigma = 1/(1+2^s) ----
#pragma unroll
        for (int p = 1; p < 8; ++p) {
            u64 s2, t2, u2, f2, y2;
            FMA2(s2, q2[p], k2[p], b2[p]);   // s = -log2e*(qk+b)
            ADD2(sa, sa, s2);                // attn: Sum s
            ADD2(t2, s2, MG2);               // t = s + M (rounds to int)
            FMA2(u2, t2, NEG1, MG2);         // u = M - t  (exact)
            ADD2(f2, s2, u2);                // f = s - i, f in [-0.5, 0.5]
            FMA2(y2, C3p, f2, C2p);          // Horner 2^f
            FMA2(y2, y2, f2, C1p);
            FMA2(y2, y2, f2, ONE2);
            float tl, th, yl, yh;
            UNPACK2(tl, th, t2);
            UNPACK2(yl, yh, y2);
            u32 pl = __float_as_uint(tl) * 8388608u + __float_as_uint(yl);  // y*2^i
            u32 ph = __float_as_uint(th) * 8388608u + __float_as_uint(yh);
            float dl = __uint_as_float(pl) + 1.0f;
            float dh = __uint_as_float(ph) + 1.0f;
            u64 g2; PACK2(g2, rcp_apx(dl), rcp_apx(dh));    // sigma
            FMA2(acc[p], m2, g2, acc[p]);
        }
        cnt += m;      // 4x cg duplication resolved by 0.25 in epilogue

        // attn: Q.K = 2*dotA + (-ln2*Sum(s) - Bp) over this thread's 16 ch
        float ax, ay, sx, sy;
        UNPACK2(ax, ay, dA);
        UNPACK2(sx, sy, sa);
        float d = 2.0f * (ax + ay) - LN2 * (sx + sy) - Bp;
        d += __shfl_xor_sync(~0u, d, 8);
        d += __shfl_xor_sync(~0u, d, 16);
        if (cg == 0)
            arow[j] = d * m;

        if (++buf == DEPTH) buf = 0;
    }

    // ---- final reductions ----
#pragma unroll
    for (int p = 0; p < 8; ++p) {
        float x, y;
        UNPACK2(x, y, acc[p]);
#pragma unroll
        for (int o = 1; o <= 4; o <<= 1) {
            x += __shfl_xor_sync(~0u, x, o);
            y += __shfl_xor_sync(~0u, y, o);
        }
        if ((l & 7) == 0) {
            float* rp = red + w * 64 + cg * 16 + 2 * p;
            rp[0] = x;
            rp[1] = y;
        }
    }
#pragma unroll
    for (int o = 1; o <= 16; o <<= 1)
        cnt += __shfl_xor_sync(~0u, cnt, o);
    if (l == 0) cbuf[w] = cnt;
    __syncthreads();

    if (tid < 64) {
        float ct = 0.25f * (cbuf[0] + cbuf[1] + cbuf[2] + cbuf[3]);
        float s  = red[tid] + red[64 + tid] + red[128 + tid] + red[192 + tid];
        // pair index within cg group: 0 -> tanh (0.5+0.5*s/ct), else poly (s/ct)
        float v = (((tid & 15) >> 1) == 0) ? (0.5f + 0.5f * s / ct) : (s / ct);
        out[(size_t)row * 64 + tid] = v;
    }
}

extern "C" void kernel_launch(void* const* d_in, const int* in_sizes, int n_in,
                              void* d_out, int out_size)
{
    const float* Q    = (const float*)d_in[0];
    const float* K    = (const float*)d_in[1];
    const float* bias = (const float*)d_in[2];
    const float* mask = (const float*)d_in[3];
    float* out  = (float*)d_out;                       // [B, I, C]
    float* attn = out + (size_t)2 * 1024 * 64;         // [B, I, J]
    attn_mlp_kernel<<<2048, THREADS>>>(Q, K, bias, mask, out, attn);
}

// round 10
// speedup vs baseline: 1.6119x; 1.6119x over previous
#include <cuda_runtime.h>

#define THREADS 128
#define Jt 32
#define NT 32          // 1024 / Jt

typedef unsigned long long u64;
typedef unsigned int u32;

#define FMA2(d,a,b,c)  asm("fma.rn.f32x2 %0, %1, %2, %3;" : "=l"(d) : "l"(a), "l"(b), "l"(c))
#define ADD2(d,a,b)    asm("add.rn.f32x2 %0, %1, %2;" : "=l"(d) : "l"(a), "l"(b))
#define PACK2(d,x,y)   asm("mov.b64 %0, {%1,%2};" : "=l"(d) : "f"(x), "f"(y))
#define UNPACK2(x,y,d) asm("mov.b64 {%0,%1}, %2;" : "=f"(x), "=f"(y) : "l"(d))

// pack two f32 -> f16x2 (la -> lo, lb -> hi)
#define CVTH2(h,la,lb) asm("cvt.rn.f16x2.f32 %0, %1, %2;" : "=r"(h) : "f"(lb), "f"(la))
// tanh on both f16 halves: ONE XU instruction
#define TANH2H(d,a)    asm("tanh.approx.f16x2 %0, %1;" : "=r"(d) : "r"(a))
// f16x2 fused multiply-add on the FMA pipe
#define HFMA2(d,a,b,c) asm("fma.rn.f16x2 %0, %1, %2, %3;" : "=r"(d) : "r"(a), "r"(b), "r"(c))
// unpack f16x2 -> two f32
#define H2TOF2(x,y,h)  asm("{ .reg .f16 l, u;\n\t mov.b32 {l, u}, %2;\n\t" \
                           "  cvt.f32.f16 %0, l;\n\t cvt.f32.f16 %1, u; }" \
                           : "=f"(x), "=f"(y) : "r"(h))

__global__ __launch_bounds__(THREADS, 3)
void attn_mlp_kernel(const float* __restrict__ Q, const float* __restrict__ K,
                     const float* __restrict__ bias, const float* __restrict__ mask,
                     float* __restrict__ out, float* __restrict__ attn)
{
    __shared__ float4 ksm[2][Jt * 17];   // double-buffered K tile, pad 17 -> conflict-free
    __shared__ float  red[512];
    __shared__ float  cbuf[2][4];

    const int tid = threadIdx.x;
    const int w   = tid >> 5, l = tid & 31;
    const int jl  = w * 8 + (l & 7);     // j within tile (0..31)
    const int cg  = l >> 3;              // channel group (16 ch each)

    const int row0 = blockIdx.x * 2;     // two i-rows per block, same b
    const int b    = row0 >> 10;

    // q prescaled by 0.5 (sigmoid = 0.5 + 0.5*tanh(x/2)), bias likewise; f32x2 packed
    u64 q20[8], q21[8], b2[8], s20[8], s21[8];
    u32 h0[8], h1[8];                    // f16x2 window accumulators (flushed every 4 tiles)
    {
        const float* q0p = Q + (size_t)row0 * 64 + cg * 16;
        const float* q1p = q0p + 64;
        const float* bp  = bias + cg * 16;
#pragma unroll
        for (int p = 0; p < 8; ++p) {
            PACK2(q20[p], 0.5f * q0p[2*p], 0.5f * q0p[2*p+1]);
            PACK2(q21[p], 0.5f * q1p[2*p], 0.5f * q1p[2*p+1]);
            PACK2(b2[p],  0.5f * bp[2*p],  0.5f * bp[2*p+1]);
            s20[p] = 0ull; s21[p] = 0ull;
            h0[p] = 0u; h1[p] = 0u;
        }
    }
    float cnt0 = 0.f, cnt1 = 0.f;

    const float4* Kg  = (const float4*)K + (size_t)b * 1024 * 16;
    const float*  m0p = mask + (size_t)row0 * 1024;
    const float*  m1p = m0p + 1024;
    float*        a0p = attn + (size_t)row0 * 1024;
    float*        a1p = a0p + 1024;

    // prefetch tile 0 into registers
    float4 kpre[4];
#pragma unroll
    for (int u = 0; u < 4; ++u) {
        int f = u * 128 + tid;
        kpre[u] = Kg[(size_t)(f >> 4) * 16 + (f & 15)];
    }

    int buf = 0;
    for (int tile = 0; tile < NT; ++tile) {
#pragma unroll
        for (int u = 0; u < 4; ++u) {
            int f = u * 128 + tid;
            ksm[buf][(f >> 4) * 17 + (f & 15)] = kpre[u];
        }
        __syncthreads();

        if (tile + 1 < NT) {
#pragma unroll
            for (int u = 0; u < 4; ++u) {
                int f = u * 128 + tid;
                kpre[u] = Kg[(size_t)((tile + 1) * Jt + (f >> 4)) * 16 + (f & 15)];
            }
        }

        u64 k2[8];
#pragma unroll
        for (int p4 = 0; p4 < 4; ++p4) {
            float4 kv = ksm[buf][jl * 17 + cg * 4 + p4];
            PACK2(k2[2*p4],   kv.x, kv.y);
            PACK2(k2[2*p4+1], kv.z, kv.w);
        }
        const int   j  = tile * Jt + jl;
        const float m0 = m0p[j], m1 = m1p[j];
        u32 m0h, m1h;                    // mask as f16x2 (0/1 exact)
        CVTH2(m0h, m0, m0);
        CVTH2(m1h, m1, m1);
        u64 dp0 = 0ull, dp1 = 0ull;

#pragma unroll
        for (int p = 0; p < 8; ++p) {
            u64 l2; float la, lb; u32 hh, th;
            // row 0: logit f32 -> f16x2 -> tanh.f16x2 -> HFMA2 accumulate (no cvt-back)
            FMA2(l2, q20[p], k2[p], b2[p]);
            FMA2(dp0, q20[p], k2[p], dp0);
            UNPACK2(la, lb, l2);
            CVTH2(hh, la, lb);
            TANH2H(th, hh);
            HFMA2(h0[p], m0h, th, h0[p]);
            // row 1
            FMA2(l2, q21[p], k2[p], b2[p]);
            FMA2(dp1, q21[p], k2[p], dp1);
            UNPACK2(la, lb, l2);
            CVTH2(hh, la, lb);
            TANH2H(th, hh);
            HFMA2(h1[p], m1h, th, h1[p]);
        }
        if (cg == 0) { cnt0 += m0; cnt1 += m1; }

        // flush f16 window accumulators to f32 every 4 tiles (keeps f16 sums <= 4)
        if ((tile & 3) == 3) {
#pragma unroll
            for (int p = 0; p < 8; ++p) {
                float x, y; u64 t2;
                H2TOF2(x, y, h0[p]); PACK2(t2, x, y); ADD2(s20[p], s20[p], t2);
                H2TOF2(x, y, h1[p]); PACK2(t2, x, y); ADD2(s21[p], s21[p], t2);
                h0[p] = 0u; h1[p] = 0u;
            }
        }

        // attention logits: q prescaled by 0.5 -> attn = 2*dot*mask (exact fp32 path)
        float dx, dy;
        UNPACK2(dx, dy, dp0); float d0 = dx + dy;
        UNPACK2(dx, dy, dp1); float d1 = dx + dy;
        d0 += __shfl_xor_sync(~0u, d0, 8);
        d0 += __shfl_xor_sync(~0u, d0, 16);
        d1 += __shfl_xor_sync(~0u, d1, 8);
        d1 += __shfl_xor_sync(~0u, d1, 16);
        if (cg == 0) {
            a0p[j] = (d0 + d0) * m0;
            a1p[j] = (d1 + d1) * m1;
        }
        buf ^= 1;
    }

    // ---- final reductions ----
#pragma unroll
    for (int p = 0; p < 8; ++p) {
        float x0, y0, x1, y1;
        UNPACK2(x0, y0, s20[p]); UNPACK2(x1, y1, s21[p]);
#pragma unroll
        for (int o = 1; o <= 4; o <<= 1) {
            x0 += __shfl_xor_sync(~0u, x0, o);
            y0 += __shfl_xor_sync(~0u, y0, o);
            x1 += __shfl_xor_sync(~0u, x1, o);
            y1 += __shfl_xor_sync(~0u, y1, o);
        }
        if ((l & 7) == 0) {
            float* rp = red + w * 128 + cg * 32;
            rp[2*p]          = x0;
            rp[2*p + 1]      = y0;
            rp[16 + 2*p]     = x1;
            rp[16 + 2*p + 1] = y1;
        }
    }
    for (int o = 1; o <= 4; o <<= 1) {
        cnt0 += __shfl_xor_sync(~0u, cnt0, o);
        cnt1 += __shfl_xor_sync(~0u, cnt1, o);
    }
    if (l == 0) { cbuf[0][w] = cnt0; cbuf[1][w] = cnt1; }
    __syncthreads();

    {
        const int r  = tid >> 6;
        const int ch = tid & 63;
        float ct = cbuf[r][0] + cbuf[r][1] + cbuf[r][2] + cbuf[r][3];
        float s  = 0.f;
#pragma unroll
        for (int ww = 0; ww < 4; ++ww)
            s += red[ww * 128 + (ch >> 4) * 32 + r * 16 + (ch & 15)];
        out[(size_t)(row0 + r) * 64 + ch] = 0.5f + 0.5f * s / ct;
    }
}

extern "C" void kernel_launch(void* const* d_in, const int* in_sizes, int n_in,
                              void* d_out, int out_size)
{
    const float* Q    = (const float*)d_in[0];
    const float* K    = (const float*)d_in[1];
    const float* bias = (const float*)d_in[2];
    const float* mask = (const float*)d_in[3];
    float* out  = (float*)d_out;                       // [B, I, C]
    float* attn = out + (size_t)2 * 1024 * 64;         // [B, I, J]
    attn_mlp_kernel<<<1024, THREADS>>>(Q, K, bias, mask, out, attn);
}

// round 11
// speedup vs baseline: 1.7926x; 1.1121x over previous
#include <cuda_runtime.h>

#define THREADS 128
#define Jt 32
#define NT 32          // 1024 / Jt
#define DEPTH 3
#define TILEB (Jt * 17 * 16)     // bytes per smem tile slot

typedef unsigned long long u64;
typedef unsigned int u32;

__device__ __forceinline__ float tanh_apx(float x) {
    float r; asm("tanh.approx.f32 %0, %1;" : "=f"(r) : "f"(x)); return r;
}
#define FMA2(d,a,b,c)  asm("fma.rn.f32x2 %0, %1, %2, %3;" : "=l"(d) : "l"(a), "l"(b), "l"(c))
#define PACK2(d,x,y)   asm("mov.b64 %0, {%1,%2};" : "=l"(d) : "f"(x), "f"(y))
#define UNPACK2(x,y,d) asm("mov.b64 {%0,%1}, %2;" : "=f"(x), "=f"(y) : "l"(d))
// cp.async with immediate byte offsets baked in (keeps register count flat)
#define CP16O(dst,doff,src,soff) \
    asm volatile("cp.async.cg.shared.global [%0+" #doff "], [%1+" #soff "], 16;" \
                 :: "r"(dst), "l"(src))
#define CPCOMMIT()     asm volatile("cp.async.commit_group;")
#define CPWAIT1()      asm volatile("cp.async.wait_group 1;")

__global__ __launch_bounds__(THREADS, 4)
void attn_mlp_kernel(const float* __restrict__ Q, const float* __restrict__ K,
                     const float* __restrict__ bias, const float* __restrict__ mask,
                     float* __restrict__ out, float* __restrict__ attn)
{
    __shared__ float4 ksm[DEPTH][Jt * 17];   // K tile ring, pad 17 -> conflict-free
    __shared__ float  red[512];
    __shared__ float  cbuf[2][4];

    const int tid = threadIdx.x;
    const int w   = tid >> 5, l = tid & 31;
    const int jl  = w * 8 + (l & 7);     // j within tile (0..31)
    const int cg  = l >> 3;              // channel group (16 ch each)

    const int row0 = blockIdx.x * 2;     // two i-rows per block, same b
    const int b    = row0 >> 10;

    // q prescaled by 0.5 (sigmoid = 0.5 + 0.5*tanh(x/2)), bias likewise; f32x2 packed
    u64 q20[8], q21[8], b2[8], s20[8], s21[8];
    {
        const float* q0p = Q + (size_t)row0 * 64 + cg * 16;
        const float* q1p = q0p + 64;
        const float* bp  = bias + cg * 16;
#pragma unroll
        for (int p = 0; p < 8; ++p) {
            PACK2(q20[p], 0.5f * q0p[2*p], 0.5f * q0p[2*p+1]);
            PACK2(q21[p], 0.5f * q1p[2*p], 0.5f * q1p[2*p+1]);
            PACK2(b2[p],  0.5f * bp[2*p],  0.5f * bp[2*p+1]);
            s20[p] = 0ull; s21[p] = 0ull;
        }
    }
    float cnt0 = 0.f, cnt1 = 0.f;

    const float*  m0p = mask + (size_t)row0 * 1024;
    const float*  m1p = m0p + 1024;
    float*        a0p = attn + (size_t)row0 * 1024;
    float*        a1p = a0p + 1024;

    // cp.async staging: 4 float4/thread/tile; one dst base + one src ptr, imm offsets
    const u32 smbase = (u32)__cvta_generic_to_shared(ksm);
    const u32 dst0   = smbase + (u32)((((tid >> 4) * 17 + (tid & 15))) << 4);
    const char* src  = (const char*)K + (size_t)b * (1024 * 256)
                       + (((tid >> 4) * 16 + (tid & 15)) << 4);

    // prologue: tiles 0 and 1 (two groups)
#pragma unroll
    for (int t = 0; t < 2; ++t) {
        u32 d = dst0 + t * TILEB;
        const char* s = src + t * 8192;
        CP16O(d, 0,    s, 0);
        CP16O(d, 2176, s, 2048);
        CP16O(d, 4352, s, 4096);
        CP16O(d, 6528, s, 6144);
        CPCOMMIT();
    }
    src += 2 * 8192;

    int buf = 0, nb = 2;
    for (int tile = 0; tile < NT; ++tile) {
        CPWAIT1();            // this tile's group complete (<=1 newer pending)
        __syncthreads();

        // prefetch tile+2 into ring slot nb (empty commit keeps group count in sync)
        if (tile + 2 < NT) {
            u32 d = dst0 + nb * TILEB;
            CP16O(d, 0,    src, 0);
            CP16O(d, 2176, src, 2048);
            CP16O(d, 4352, src, 4096);
            CP16O(d, 6528, src, 6144);
        }
        CPCOMMIT();
        src += 8192;

        // 16 channels for this thread's j, straight from padded smem as u64 pairs
        const u64* kb = (const u64*)(ksm[buf]) + jl * 34 + cg * 8;
        u64 k2[8];
#pragma unroll
        for (int p = 0; p < 8; ++p) k2[p] = kb[p];

        const int   j  = tile * Jt + jl;
        const float m0 = m0p[j], m1 = m1p[j];
        u64 m20, m21; PACK2(m20, m0, m0); PACK2(m21, m1, m1);
        u64 dp0 = 0ull, dp1 = 0ull;

#pragma unroll
        for (int p = 0; p < 8; ++p) {
            u64 l2, t2; float la, lb;
            FMA2(l2, q20[p], k2[p], b2[p]);
            FMA2(dp0, q20[p], k2[p], dp0);
            UNPACK2(la, lb, l2);
            PACK2(t2, tanh_apx(la), tanh_apx(lb));
            FMA2(s20[p], m20, t2, s20[p]);

            FMA2(l2, q21[p], k2[p], b2[p]);
            FMA2(dp1, q21[p], k2[p], dp1);
            UNPACK2(la, lb, l2);
            PACK2(t2, tanh_apx(la), tanh_apx(lb));
            FMA2(s21[p], m21, t2, s21[p]);
        }
        if (cg == 0) { cnt0 += m0; cnt1 += m1; }

        // attention logits: q prescaled by 0.5 -> attn = 2*dot*mask (exact fp32 path)
        float dx, dy;
        UNPACK2(dx, dy, dp0); float d0 = dx + dy;
        UNPACK2(dx, dy, dp1); float d1 = dx + dy;
        d0 += __shfl_xor_sync(~0u, d0, 8);
        d0 += __shfl_xor_sync(~0u, d0, 16);
        d1 += __shfl_xor_sync(~0u, d1, 8);
        d1 += __shfl_xor_sync(~0u, d1, 16);
        if (cg == 0) {
            a0p[j] = (d0 + d0) * m0;
            a1p[j] = (d1 + d1) * m1;
        }
        buf = (buf == DEPTH - 1) ? 0 : buf + 1;
        nb  = (nb  == DEPTH - 1) ? 0 : nb + 1;
    }

    // ---- final reductions ----
#pragma unroll
    for (int p = 0; p < 8; ++p) {
        float x0, y0, x1, y1;
        UNPACK2(x0, y0, s20[p]); UNPACK2(x1, y1, s21[p]);
#pragma unroll
        for (int o = 1; o <= 4; o <<= 1) {
            x0 += __shfl_xor_sync(~0u, x0, o);
            y0 += __shfl_xor_sync(~0u, y0, o);
            x1 += __shfl_xor_sync(~0u, x1, o);
            y1 += __shfl_xor_sync(~0u, y1, o);
        }
        if ((l & 7) == 0) {
            float* rp = red + w * 128 + cg * 32;
            rp[2*p]          = x0;
            rp[2*p + 1]      = y0;
            rp[16 + 2*p]     = x1;
            rp[16 + 2*p + 1] = y1;
        }
    }
    for (int o = 1; o <= 4; o <<= 1) {
        cnt0 += __shfl_xor_sync(~0u, cnt0, o);
        cnt1 += __shfl_xor_sync(~0u, cnt1, o);
    }
    if (l == 0) { cbuf[0][w] = cnt0; cbuf[1][w] = cnt1; }
    __syncthreads();

    {
        const int r  = tid >> 6;
        const int ch = tid & 63;
        float ct = cbuf[r][0] + cbuf[r][1] + cbuf[r][2] + cbuf[r][3];
        float s  = 0.f;
#pragma unroll
        for (int ww = 0; ww < 4; ++ww)
            s += red[ww * 128 + (ch >> 4) * 32 + r * 16 + (ch & 15)];
        out[(size_t)(row0 + r) * 64 + ch] = 0.5f + 0.5f * s / ct;
    }
}

extern "C" void kernel_launch(void* const* d_in, const int* in_sizes, int n_in,
                              void* d_out, int out_size)
{
    const float* Q    = (const float*)d_in[0];
    const float* K    = (const float*)d_in[1];
    const float* bias = (const float*)d_in[2];
    const float* mask = (const float*)d_in[3];
    float* out  = (float*)d_out;                       // [B, I, C]
    float* attn = out + (size_t)2 * 1024 * 64;         // [B, I, J]
    attn_mlp_kernel<<<1024, THREADS>>>(Q, K, bias, mask, out, attn);
}

// round 12
// speedup vs baseline: 1.8848x; 1.0514x over previous
#include <cuda_runtime.h>

#define THREADS 128
#define Jt 32
#define NT 32          // 1024 / Jt
#define DEPTH 3
#define TILEB (Jt * 17 * 16)     // bytes per smem tile slot

typedef unsigned long long u64;
typedef unsigned int u32;

#define FMA2(d,a,b,c)  asm("fma.rn.f32x2 %0, %1, %2, %3;" : "=l"(d) : "l"(a), "l"(b), "l"(c))
#define PACK2(d,x,y)   asm("mov.b64 %0, {%1,%2};" : "=l"(d) : "f"(x), "f"(y))
#define UNPACK2(x,y,d) asm("mov.b64 {%0,%1}, %2;" : "=f"(x), "=f"(y) : "l"(d))
// two f32 -> f16x2 (la -> lo, lb -> hi)
#define CVTH2(h,la,lb) asm("cvt.rn.f16x2.f32 %0, %1, %2;" : "=r"(h) : "f"(lb), "f"(la))
// tanh on both f16 halves: ONE XU instruction for two elements
#define TANH2H(d,a)    asm("tanh.approx.f16x2 %0, %1;" : "=r"(d) : "r"(a))
// f16x2 fused multiply-add (FMA pipe)
#define HFMA2(d,a,b,c) asm("fma.rn.f16x2 %0, %1, %2, %3;" : "=r"(d) : "r"(a), "r"(b), "r"(c))
// unpack f16x2 -> two f32
#define H2TOF2(x,y,h)  asm("{ .reg .f16 lo, hi;\n\t mov.b32 {lo, hi}, %2;\n\t" \
                           "  cvt.f32.f16 %0, lo;\n\t cvt.f32.f16 %1, hi; }" \
                           : "=f"(x), "=f"(y) : "r"(h))
// cp.async with immediate byte offsets
#define CP16O(dst,doff,src,soff) \
    asm volatile("cp.async.cg.shared.global [%0+" #doff "], [%1+" #soff "], 16;" \
                 :: "r"(dst), "l"(src))
#define CPCOMMIT()     asm volatile("cp.async.commit_group;")
#define CPWAIT1()      asm volatile("cp.async.wait_group 1;")

__global__ __launch_bounds__(THREADS, 4)
void attn_mlp_kernel(const float* __restrict__ Q, const float* __restrict__ K,
                     const float* __restrict__ bias, const float* __restrict__ mask,
                     float* __restrict__ out, float* __restrict__ attn)
{
    __shared__ float4 ksm[DEPTH][Jt * 17];   // K tile ring, pad 17 -> conflict-free
    __shared__ float  red[512];
    __shared__ float  cbuf[2][4];

    const int tid = threadIdx.x;
    const int w   = tid >> 5, l = tid & 31;
    const int jl  = w * 8 + (l & 7);     // j within tile (0..31)
    const int cg  = l >> 3;              // channel group (16 ch each)

    const int row0 = blockIdx.x * 2;     // two i-rows per block, same b
    const int b    = row0 >> 10;

    // q prescaled by 0.5 (sigmoid = 0.5 + 0.5*tanh(x/2)), bias likewise; f32x2 packed
    u64 q20[8], q21[8], b2[8];
    u32 h0[8], h1[8];                    // f16x2 accumulators, whole-row (no flush)
    {
        const float* q0p = Q + (size_t)row0 * 64 + cg * 16;
        const float* q1p = q0p + 64;
        const float* bp  = bias + cg * 16;
#pragma unroll
        for (int p = 0; p < 8; ++p) {
            PACK2(q20[p], 0.5f * q0p[2*p], 0.5f * q0p[2*p+1]);
            PACK2(q21[p], 0.5f * q1p[2*p], 0.5f * q1p[2*p+1]);
            PACK2(b2[p],  0.5f * bp[2*p],  0.5f * bp[2*p+1]);
            h0[p] = 0u; h1[p] = 0u;
        }
    }
    float cnt0 = 0.f, cnt1 = 0.f;

    const float*  m0p = mask + (size_t)row0 * 1024;
    const float*  m1p = m0p + 1024;
    float*        a0p = attn + (size_t)row0 * 1024;
    float*        a1p = a0p + 1024;

    // cp.async staging: 4 float4/thread/tile; one dst base + one src ptr, imm offsets
    const u32 smbase = (u32)__cvta_generic_to_shared(ksm);
    const u32 dst0   = smbase + (u32)((((tid >> 4) * 17 + (tid & 15))) << 4);
    const char* src  = (const char*)K + (size_t)b * (1024 * 256)
                       + (((tid >> 4) * 16 + (tid & 15)) << 4);

    // prologue: tiles 0 and 1 (two groups)
#pragma unroll
    for (int t = 0; t < 2; ++t) {
        u32 d = dst0 + t * TILEB;
        const char* s = src + t * 8192;
        CP16O(d, 0,    s, 0);
        CP16O(d, 2176, s, 2048);
        CP16O(d, 4352, s, 4096);
        CP16O(d, 6528, s, 6144);
        CPCOMMIT();
    }
    src += 2 * 8192;

    int buf = 0, nb = 2;
    for (int tile = 0; tile < NT; ++tile) {
        CPWAIT1();            // this tile's group complete (<=1 newer pending)
        __syncthreads();

        // prefetch tile+2 into ring slot nb (empty commit keeps group count in sync)
        if (tile + 2 < NT) {
            u32 d = dst0 + nb * TILEB;
            CP16O(d, 0,    src, 0);
            CP16O(d, 2176, src, 2048);
            CP16O(d, 4352, src, 4096);
            CP16O(d, 6528, src, 6144);
        }
        CPCOMMIT();
        src += 8192;

        // 16 channels for this thread's j, straight from padded smem as u64 pairs
        const u64* kb = (const u64*)(ksm[buf]) + jl * 34 + cg * 8;
        u64 k2[8];
#pragma unroll
        for (int p = 0; p < 8; ++p) k2[p] = kb[p];

        const int   j  = tile * Jt + jl;
        const float m0 = m0p[j], m1 = m1p[j];
        u32 m0h, m1h;                    // mask 0/1 exact in f16
        CVTH2(m0h, m0, m0);
        CVTH2(m1h, m1, m1);
        u64 dp0 = 0ull, dp1 = 0ull;

#pragma unroll
        for (int p = 0; p < 8; ++p) {
            u64 l2; float la, lb; u32 hh, th;
            // row 0: f32 logit -> one CVT -> one tanh.f16x2 -> HFMA2 accumulate
            FMA2(l2, q20[p], k2[p], b2[p]);
            FMA2(dp0, q20[p], k2[p], dp0);
            UNPACK2(la, lb, l2);
            CVTH2(hh, la, lb);
            TANH2H(th, hh);
            HFMA2(h0[p], m0h, th, h0[p]);
            // row 1
            FMA2(l2, q21[p], k2[p], b2[p]);
            FMA2(dp1, q21[p], k2[p], dp1);
            UNPACK2(la, lb, l2);
            CVTH2(hh, la, lb);
            TANH2H(th, hh);
            HFMA2(h1[p], m1h, th, h1[p]);
        }
        if (cg == 0) { cnt0 += m0; cnt1 += m1; }

        // attention logits: q prescaled by 0.5 -> attn = 2*dot*mask (exact fp32 path)
        float dx, dy;
        UNPACK2(dx, dy, dp0); float d0 = dx + dy;
        UNPACK2(dx, dy, dp1); float d1 = dx + dy;
        d0 += __shfl_xor_sync(~0u, d0, 8);
        d0 += __shfl_xor_sync(~0u, d0, 16);
        d1 += __shfl_xor_sync(~0u, d1, 8);
        d1 += __shfl_xor_sync(~0u, d1, 16);
        if (cg == 0) {
            a0p[j] = (d0 + d0) * m0;
            a1p[j] = (d1 + d1) * m1;
        }
        buf = (buf == DEPTH - 1) ? 0 : buf + 1;
        nb  = (nb  == DEPTH - 1) ? 0 : nb + 1;
    }

    // ---- final reductions (convert f16x2 accumulators once, then as R11) ----
#pragma unroll
    for (int p = 0; p < 8; ++p) {
        float x0, y0, x1, y1;
        H2TOF2(x0, y0, h0[p]);
        H2TOF2(x1, y1, h1[p]);
#pragma unroll
        for (int o = 1; o <= 4; o <<= 1) {
            x0 += __shfl_xor_sync(~0u, x0, o);
            y0 += __shfl_xor_sync(~0u, y0, o);
            x1 += __shfl_xor_sync(~0u, x1, o);
            y1 += __shfl_xor_sync(~0u, y1, o);
        }
        if ((l & 7) == 0) {
            float* rp = red + w * 128 + cg * 32;
            rp[2*p]          = x0;
            rp[2*p + 1]      = y0;
            rp[16 + 2*p]     = x1;
            rp[16 + 2*p + 1] = y1;
        }
    }
    for (int o = 1; o <= 4; o <<= 1) {
        cnt0 += __shfl_xor_sync(~0u, cnt0, o);
        cnt1 += __shfl_xor_sync(~0u, cnt1, o);
    }
    if (l == 0) { cbuf[0][w] = cnt0; cbuf[1][w] = cnt1; }
    __syncthreads();

    {
        const int r  = tid >> 6;
        const int ch = tid & 63;
        float ct = cbuf[r][0] + cbuf[r][1] + cbuf[r][2] + cbuf[r][3];
        float s  = 0.f;
#pragma unroll
        for (int ww = 0; ww < 4; ++ww)
            s += red[ww * 128 + (ch >> 4) * 32 + r * 16 + (ch & 15)];
        out[(size_t)(row0 + r) * 64 + ch] = 0.5f + 0.5f * s / ct;
    }
}

extern "C" void kernel_launch(void* const* d_in, const int* in_sizes, int n_in,
                              void* d_out, int out_size)
{
    const float* Q    = (const float*)d_in[0];
    const float* K    = (const float*)d_in[1];
    const float* bias = (const float*)d_in[2];
    const float* mask = (const float*)d_in[3];
    float* out  = (float*)d_out;                       // [B, I, C]
    float* attn = out + (size_t)2 * 1024 * 64;         // [B, I, J]
    attn_mlp_kernel<<<1024, THREADS>>>(Q, K, bias, mask, out, attn);
}